// round 2
// baseline (speedup 1.0000x reference)
#include <cuda_runtime.h>

// E90 dual-rate gated linear-attention scan.
// Shapes (fixed by the problem): T=2048, B=8, H=16, KF=32, VF=64, KS=128, VS=64.
// One CTA per (b,h) head-instance; 256 threads; states live in registers as
// packed f32x2; per-step vectors staged in shared (double-buffered) with
// k/q values pre-replicated so broadcast LDS feeds fma.rn.f32x2 directly.

#define T_DIM 2048
#define B_DIM 8
#define H_DIM 16
#define BH    128
#define KF    32
#define VF    64
#define KS    128
#define VS    64

typedef unsigned long long u64;

__device__ __forceinline__ u64 pack2(float x, float y) {
    u64 u; asm("mov.b64 %0, {%1,%2};" : "=l"(u) : "f"(x), "f"(y)); return u;
}
__device__ __forceinline__ u64 dup2(float x) { return pack2(x, x); }
__device__ __forceinline__ u64 ffma2(u64 a, u64 b, u64 c) {
    u64 d; asm("fma.rn.f32x2 %0, %1, %2, %3;" : "=l"(d) : "l"(a), "l"(b), "l"(c)); return d;
}
__device__ __forceinline__ u64 fmul2(u64 a, u64 b) {
    u64 d; asm("mul.rn.f32x2 %0, %1, %2;" : "=l"(d) : "l"(a), "l"(b)); return d;
}
__device__ __forceinline__ u64 fadd2(u64 a, u64 b) {
    u64 d; asm("add.rn.f32x2 %0, %1, %2;" : "=l"(d) : "l"(a), "l"(b)); return d;
}

struct __align__(16) Stage {
    u64 kqf[KF * 2];    // [row*2+0] = (kf,kf), [row*2+1] = (qf,qf)   512 B
    u64 kqs[KS * 2];    // [row*2+0] = (ks,ks), [row*2+1] = (qs,qs)   2048 B
    u64 vf2[VF / 2];    // v_fast column pairs                         256 B
    u64 vs2[VS / 2];    // g * v_slow column pairs                     256 B
    u64 scal[4];        // (df,df), (a,a), (mf,mf), (ms,ms)            32 B
};

// ---- staging: write one timestep's vectors (held in regs) into a stage buffer
#define STAGE_STORE(sg, vA, vB, vB2, vG, S0, S1, S2, S3, S4) do {              \
    if (tid < 32)       (sg)->kqf[tid * 2]           = dup2(vA);               \
    else if (tid < 64)  (sg)->kqf[(tid - 32) * 2 + 1] = dup2(vA);              \
    else if (tid < 192) (sg)->kqs[(tid - 64) * 2]     = dup2(vA);              \
    else                (sg)->kqs[(tid - 192) * 2 + 1] = dup2(vA);             \
    if (tid < 64)       (sg)->kqs[(64 + tid) * 2 + 1] = dup2(vB);              \
    else if (tid < 96)  (sg)->vf2[tid - 64] = pack2((vB2).x, (vB2).y);         \
    else if (tid < 128) (sg)->vs2[tid - 96] = pack2((vG) * (vB2).x, (vG) * (vB2).y); \
    if (tid == 128) {                                                          \
        float a_ = 1.0f + (S2) * ((S1) - 1.0f);                                \
        (sg)->scal[0] = dup2(S0); (sg)->scal[1] = dup2(a_);                    \
        (sg)->scal[2] = dup2(S3); (sg)->scal[3] = dup2(S4);                    \
    }                                                                          \
} while (0)

// ---- prefetch one timestep's source values into the PI register slot
#define PREFETCH(PI, TL) do {                                                  \
    size_t _t = (size_t)(TL);                                                  \
    pA[PI] = __ldg(srcA + _t * strideA);                                       \
    if (tid < 64) pB[PI] = __ldg(srcB + _t * (BH * KS));                       \
    else if (tid < 128) {                                                      \
        pB2[PI] = __ldg(srcB2 + _t * (BH * VF / 2));                           \
        if (tid >= 96) pg[PI] = __ldg(srcG + _t * BH);                         \
    }                                                                          \
    if (tid == 128) {                                                          \
        psc[PI][0] = __ldg(decay_fast + _t * BH + bh);                         \
        psc[PI][1] = __ldg(decay_slow + _t * BH + bh);                         \
        psc[PI][2] = __ldg(slow_gate + _t * BH + bh);                          \
        psc[PI][3] = __ldg(mix_fast + _t * BH + bh);                           \
        psc[PI][4] = __ldg(mix_slow + _t * BH + bh);                           \
    }                                                                          \
} while (0)

// ---- one scan iteration. PC = t&1 (compute buffer), PN = (t+1)&1 (stage buffer).
// Note (t-1)&1 == (t+1)&1 == PN.
#define ITER(TCUR, PC, PN) do {                                                \
    Stage* sgw = &stage[PN];                                                   \
    STAGE_STORE(sgw, pA[PN], pB[PN], pB2[PN], pg[PN],                          \
                psc[PN][0], psc[PN][1], psc[PN][2], psc[PN][3], psc[PN][4]);   \
    int _tl = (TCUR) + 3; if (_tl > T_DIM - 1) _tl = T_DIM - 1;                \
    PREFETCH(PN, _tl);                                                         \
    if ((TCUR) > 0 && tid < 32) {                                              \
        u64 s = red[PN][0][lane];                                              \
        _Pragma("unroll")                                                      \
        for (int k2 = 1; k2 < 8; k2++) s = fadd2(s, red[PN][k2][lane]);        \
        ((u64*)out_y)[((size_t)((TCUR) - 1) * BH + bh) * 32 + lane] = s;       \
    }                                                                          \
    const Stage* sg = &stage[PC];                                              \
    ulonglong2 sc0 = *(const ulonglong2*)&sg->scal[0];  /* (df2, a2)   */      \
    ulonglong2 sc1 = *(const ulonglong2*)&sg->scal[2];  /* (mf2, ms2)  */      \
    u64 vf_ = ((const u64*)sg->vf2)[lane];                                     \
    u64 vs_ = ((const u64*)sg->vs2)[lane];                                     \
    u64 accf = 0ull, accs = 0ull;                                              \
    _Pragma("unroll")                                                          \
    for (int i = 0; i < 4; i++) {                                              \
        ulonglong2 kq = *(const ulonglong2*)&sg->kqf[(kg * 4 + i) * 2];        \
        Sf[i] = ffma2(sc0.x, Sf[i], fmul2(kq.x, vf_));                         \
        accf  = ffma2(kq.y, Sf[i], accf);                                      \
    }                                                                          \
    _Pragma("unroll")                                                          \
    for (int i = 0; i < 16; i++) {                                             \
        ulonglong2 kq = *(const ulonglong2*)&sg->kqs[(kg * 16 + i) * 2];       \
        Ss[i] = ffma2(sc0.y, Ss[i], fmul2(kq.x, vs_));                         \
        accs  = ffma2(kq.y, Ss[i], accs);                                      \
    }                                                                          \
    red[PC][kg][lane] = ffma2(sc1.y, accs, fmul2(sc1.x, accf));                \
    __syncthreads();                                                           \
} while (0)

__global__ void __launch_bounds__(256, 1)
e90_dualrate_kernel(const float* __restrict__ k_fast,
                    const float* __restrict__ v_fast,
                    const float* __restrict__ q_fast,
                    const float* __restrict__ decay_fast,
                    const float* __restrict__ k_slow,
                    const float* __restrict__ v_slow,
                    const float* __restrict__ q_slow,
                    const float* __restrict__ decay_slow,
                    const float* __restrict__ slow_gate,
                    const float* __restrict__ mix_fast,
                    const float* __restrict__ mix_slow,
                    const float* __restrict__ S_fast0,
                    const float* __restrict__ S_slow0,
                    float* __restrict__ out_Sf,   // may be null
                    float* __restrict__ out_Ss,   // may be null
                    float* __restrict__ out_y) {
    __shared__ Stage stage[2];
    __shared__ u64 red[2][8][32];

    const int tid  = threadIdx.x;
    const int lane = tid & 31;   // column pair: cols (2*lane, 2*lane+1)
    const int kg   = tid >> 5;   // k-row group (warp id)
    const int bh   = blockIdx.x; // b*H + h

    // --- per-thread source pointers for staging tasks ---
    // taskA (all 256 threads): one scalar per step.
    const float* srcA;
    int strideA;
    if (tid < 32)       { srcA = k_fast + bh * KF + tid;          strideA = BH * KF; }
    else if (tid < 64)  { srcA = q_fast + bh * KF + (tid - 32);   strideA = BH * KF; }
    else if (tid < 192) { srcA = k_slow + bh * KS + (tid - 64);   strideA = BH * KS; }
    else                { srcA = q_slow + bh * KS + (tid - 192);  strideA = BH * KS; }
    // taskB (tid < 128): qs rows 64..127 (tid<64), v_fast pairs (64<=tid<96),
    // v_slow pairs + gate (96<=tid<128).
    const float*  srcB  = q_slow + bh * KS + 64 + tid;        // valid use only if tid<64
    const float2* srcB2 = nullptr;
    const float*  srcG  = slow_gate + bh;
    if (tid >= 64 && tid < 96)  srcB2 = (const float2*)(v_fast + bh * VF) + (tid - 64);
    if (tid >= 96 && tid < 128) srcB2 = (const float2*)(v_slow + bh * VS) + (tid - 96);

    // --- prefetch register slots (parity-indexed, resolved at compile time) ---
    float  pA[2];
    float  pB[2];
    float2 pB2[2];
    float  pg[2];
    float  psc[2][5];

    // --- register-resident states ---
    u64 Sf[4];
    u64 Ss[16];

    // --- prologue: stage t=0 directly, prefetch t=1 (slot 1) and t=2 (slot 0) ---
    {
        float a0 = __ldg(srcA);
        float b0 = 0.0f; float2 b20 = make_float2(0.0f, 0.0f); float g0 = 0.0f;
        if (tid < 64) b0 = __ldg(srcB);
        else if (tid < 128) { b20 = __ldg(srcB2); if (tid >= 96) g0 = __ldg(srcG); }
        float s0 = 0, s1 = 0, s2 = 0, s3 = 0, s4 = 0;
        if (tid == 128) {
            s0 = __ldg(decay_fast + bh); s1 = __ldg(decay_slow + bh);
            s2 = __ldg(slow_gate + bh);  s3 = __ldg(mix_fast + bh);
            s4 = __ldg(mix_slow + bh);
        }
        STAGE_STORE(&stage[0], a0, b0, b20, g0, s0, s1, s2, s3, s4);
    }
    PREFETCH(1, 1);
    PREFETCH(0, 2);

#pragma unroll
    for (int i = 0; i < 4; i++)
        Sf[i] = ((const u64*)S_fast0)[((size_t)bh * KF + kg * 4 + i) * 32 + lane];
#pragma unroll
    for (int i = 0; i < 16; i++)
        Ss[i] = ((const u64*)S_slow0)[((size_t)bh * KS + kg * 16 + i) * 32 + lane];

    __syncthreads();

    // --- main scan loop: one __syncthreads per step, parity unrolled x2 ---
    for (int t = 0; t < T_DIM; t += 2) {
        ITER(t,     0, 1);
        ITER(t + 1, 1, 0);
    }

    // --- epilogue: reduce+store y[T-1] ((T-1)&1 == 1), write final states ---
    if (tid < 32) {
        u64 s = red[1][0][lane];
#pragma unroll
        for (int k2 = 1; k2 < 8; k2++) s = fadd2(s, red[1][k2][lane]);
        ((u64*)out_y)[((size_t)(T_DIM - 1) * BH + bh) * 32 + lane] = s;
    }
    if (out_Sf) {
#pragma unroll
        for (int i = 0; i < 4; i++)
            ((u64*)out_Sf)[((size_t)bh * KF + kg * 4 + i) * 32 + lane] = Sf[i];
    }
    if (out_Ss) {
#pragma unroll
        for (int i = 0; i < 16; i++)
            ((u64*)out_Ss)[((size_t)bh * KS + kg * 16 + i) * 32 + lane] = Ss[i];
    }
}

extern "C" void kernel_launch(void* const* d_in, const int* in_sizes, int n_in,
                              void* d_out, int out_size) {
    const float* k_fast     = (const float*)d_in[0];
    const float* v_fast     = (const float*)d_in[1];
    const float* q_fast     = (const float*)d_in[2];
    const float* decay_fast = (const float*)d_in[3];
    const float* k_slow     = (const float*)d_in[4];
    const float* v_slow     = (const float*)d_in[5];
    const float* q_slow     = (const float*)d_in[6];
    const float* decay_slow = (const float*)d_in[7];
    const float* slow_gate  = (const float*)d_in[8];
    const float* mix_fast   = (const float*)d_in[9];
    const float* mix_slow   = (const float*)d_in[10];
    const float* S_fast0    = (const float*)d_in[11];
    const float* S_slow0    = (const float*)d_in[12];

    float* out = (float*)d_out;
    const int sf_n = BH * KF * VF;        // 262144
    const int ss_n = BH * KS * VS;        // 1048576
    const int y_n  = T_DIM * BH * VF;     // 16777216

    float *oSf, *oSs, *oY;
    if (out_size >= sf_n + ss_n + y_n) {
        // tuple (S_f_final, S_s_final, output) flattened in return order
        oSf = out;
        oSs = out + sf_n;
        oY  = out + sf_n + ss_n;
    } else {
        // output only
        oSf = nullptr;
        oSs = nullptr;
        oY  = out;
    }

    e90_dualrate_kernel<<<BH, 256>>>(k_fast, v_fast, q_fast, decay_fast,
                                     k_slow, v_slow, q_slow, decay_slow,
                                     slow_gate, mix_fast, mix_slow,
                                     S_fast0, S_slow0,
                                     oSf, oSs, oY);
}